// round 14
// baseline (speedup 1.0000x reference)
#include <cuda_runtime.h>
#include <math.h>

#define B 512
#define S 256
#define H 256
#define U 10
#define G4 1024   // 4*H
#define B_PERSIST 384   // batches whose enc_out slice is held L2-resident (96 MB)

// ---------------- device scratch (static allocations only) ----------------
__device__ float g_enc_out[B * S * H];   // [b][s][h]  134 MB
__device__ float g_encW1[B * U * S];     // [b][u][s]  5 MB
__device__ float g_Wenc[257 * G4];       // interleaved gate cols
__device__ float g_Wdec[513 * G4];
__device__ float g_bias_enc[G4];
__device__ float g_bias_dec[G4];
__device__ float g_hA[B * H];
__device__ float g_hB[B * H];
__device__ float g_c[B * H];
__device__ float g_ext[B * 257];         // decoder lstm extra input: [di(256) | dec_in(1)]
__device__ float g_decnext[B];           // staged teacher-forced input
__device__ float g_lossbuf[S * B];
__device__ int   g_y64;

// ---------------- 256-bit L2 eviction-priority loads ------------------------
__device__ __forceinline__ void ld8_last(const float* p, float f[8])
{
    unsigned long long q0, q1, q2, q3;
    asm volatile("ld.global.nc.L2::evict_last.v4.b64 {%0,%1,%2,%3}, [%4];"
                 : "=l"(q0), "=l"(q1), "=l"(q2), "=l"(q3) : "l"(p));
    f[0] = __uint_as_float((unsigned)q0); f[1] = __uint_as_float((unsigned)(q0 >> 32));
    f[2] = __uint_as_float((unsigned)q1); f[3] = __uint_as_float((unsigned)(q1 >> 32));
    f[4] = __uint_as_float((unsigned)q2); f[5] = __uint_as_float((unsigned)(q2 >> 32));
    f[6] = __uint_as_float((unsigned)q3); f[7] = __uint_as_float((unsigned)(q3 >> 32));
}
__device__ __forceinline__ void ld8_first(const float* p, float f[8])
{
    unsigned long long q0, q1, q2, q3;
    asm volatile("ld.global.nc.L2::evict_first.v4.b64 {%0,%1,%2,%3}, [%4];"
                 : "=l"(q0), "=l"(q1), "=l"(q2), "=l"(q3) : "l"(p));
    f[0] = __uint_as_float((unsigned)q0); f[1] = __uint_as_float((unsigned)(q0 >> 32));
    f[2] = __uint_as_float((unsigned)q1); f[3] = __uint_as_float((unsigned)(q1 >> 32));
    f[4] = __uint_as_float((unsigned)q2); f[5] = __uint_as_float((unsigned)(q2 >> 32));
    f[6] = __uint_as_float((unsigned)q3); f[7] = __uint_as_float((unsigned)(q3 >> 32));
}

// ---------------- XLA-matching transcendentals -----------------------------
__device__ __forceinline__ float exp_p(float x)
{
    x = fminf(fmaxf(x, -87.0f), 87.0f);
    float t = fmaf(x, 1.44269504088896341f, 12582912.0f);
    float n = t - 12582912.0f;
    float r = fmaf(n, -0.693359375f, x);
    r = fmaf(n, 2.12194440e-4f, r);
    float p = 1.9875691500e-4f;
    p = fmaf(p, r, 1.3981999507e-3f);
    p = fmaf(p, r, 8.3334519073e-3f);
    p = fmaf(p, r, 4.1665795894e-2f);
    p = fmaf(p, r, 1.6666665459e-1f);
    p = fmaf(p, r, 5.0000001201e-1f);
    float res = fmaf(r * r, p, r) + 1.0f;
    int i = (int)n;
    float scale = __int_as_float((i + 127) << 23);
    return res * scale;
}

__device__ __forceinline__ float tanh_xla(float x)
{
    if (fabsf(x) < 0.0004f) return x;
    float xc = fminf(fmaxf(x, -7.90531110763549805f), 7.90531110763549805f);
    float x2 = xc * xc;
    float np = fmaf(x2, -2.76076847742355e-16f, 2.00018790482477e-13f);
    np = fmaf(x2, np, -8.60467152213735e-11f);
    np = fmaf(x2, np, 5.12229709037114e-08f);
    np = fmaf(x2, np, 1.48572235717979e-05f);
    np = fmaf(x2, np, 6.37261928875436e-04f);
    np = fmaf(x2, np, 4.89352455891786e-03f);
    np = np * xc;
    float dp = fmaf(x2, 1.19825839466702e-06f, 1.18534705686654e-04f);
    dp = fmaf(x2, dp, 2.26843463243900e-03f);
    dp = fmaf(x2, dp, 4.89352518554385e-03f);
    return __fdiv_rn(np, dp);
}

__device__ __forceinline__ float sig_xla(float x)
{
    return fmaf(0.5f, tanh_xla(0.5f * x), 0.5f);
}

#define KAHAN_ADD(acc, comp, val)            \
    do {                                     \
        float _y = (val) - (comp);           \
        float _t = (acc) + _y;               \
        (comp) = (_t - (acc)) - _y;          \
        (acc) = _t;                          \
    } while (0)

// ---------------- weight prep: interleave gate columns --------------------
__global__ void prep_kernel(const float* __restrict__ eWih, const float* __restrict__ eWhh,
                            const float* __restrict__ ebih, const float* __restrict__ ebhh,
                            const float* __restrict__ dWih, const float* __restrict__ dWhh,
                            const float* __restrict__ dbih, const float* __restrict__ dbhh)
{
    int idx = blockIdx.x * blockDim.x + threadIdx.x;
    if (idx >= 513 * G4) return;
    int k = idx >> 10, j = idx & 1023;
    int h = j >> 2, g = j & 3;
    int r = g * 256 + h;
    float wd = (k < 256) ? dWhh[r * 256 + k] : dWih[r * 257 + (k - 256)];
    g_Wdec[idx] = wd;
    if (k < 257) {
        float we = (k < 256) ? eWhh[r * 256 + k] : eWih[r];
        g_Wenc[idx] = we;
    }
    if (k == 0) {
        g_bias_enc[j] = ebih[r] + ebhh[r];
        g_bias_dec[j] = dbih[r] + dbhh[r];
    }
}

__global__ void init_kernel()
{
    int idx = blockIdx.x * blockDim.x + threadIdx.x;
    if (idx < B * H) { g_hA[idx] = 0.f; g_c[idx] = 0.f; }
    if (idx < B)     { g_decnext[idx] = 0.f; }
}

__global__ void detect_y(const void* __restrict__ y)
{
    const int* yi = (const int*)y;
    int all0 = 1;
    for (int i = 1; i < 64; i += 2) if (yi[i] != 0) all0 = 0;
    g_y64 = all0;
}

// ---------------- fused GEMM + LSTM pointwise step -------------------------
// 32x32 tile, 128 threads, 2x4 microtile, register-prefetch pipeline.
// Per-output k-summation order identical to R9 (bitwise-same numerics);
// smaller CTAs raise occupancy and improve 148-SM wave balance.
__global__ __launch_bounds__(128) void lstm_step(const float* __restrict__ xptr,
                                                 int KMAIN, int is_enc, int t, int parity)
{
    const float* h_in  = parity ? g_hB : g_hA;
    float*       h_out = parity ? g_hA : g_hB;
    const float* W     = is_enc ? g_Wenc : g_Wdec;
    const float* bias  = is_enc ? g_bias_enc : g_bias_dec;

    __shared__ float As_t[64][34];   // [k][row], 32 rows padded to 34
    __shared__ float Ws[64][32];

    int rb = blockIdx.y * 32, jc = blockIdx.x * 32;
    int tid = threadIdx.x;
    int tx = tid & 7, ty = tid >> 3;        // tx 0..7 (4 cols each), ty 0..15 (2 rows)

    // loader indices
    // A h-region: 512 float4 over 4 passes of 128: r = idx>>4, q = idx&15
    int ar0 = tid >> 4,           aq0 = tid & 15;
    int ar1 = (tid + 128) >> 4,   aq1 = (tid + 128) & 15;
    int ar2 = (tid + 256) >> 4,   aq2 = (tid + 256) & 15;
    int ar3 = (tid + 384) >> 4,   aq3 = (tid + 384) & 15;
    // W: 512 float4 over 4 passes: k = idx>>3, q = idx&7
    int wk0 = tid >> 3,           wq0 = tid & 7;
    int wk1 = (tid + 128) >> 3,   wq1 = (tid + 128) & 7;
    int wk2 = (tid + 256) >> 3,   wq2 = (tid + 256) & 7;
    int wk3 = (tid + 384) >> 3,   wq3 = (tid + 384) & 7;

    float acc[2][4] = {};
    float cmp[2][4] = {};

    // ---- load tile 0 (always h region) ----
    {
        float4 v0 = *(const float4*)&h_in[(rb + ar0) * 256 + aq0 * 4];
        float4 v1 = *(const float4*)&h_in[(rb + ar1) * 256 + aq1 * 4];
        float4 v2 = *(const float4*)&h_in[(rb + ar2) * 256 + aq2 * 4];
        float4 v3 = *(const float4*)&h_in[(rb + ar3) * 256 + aq3 * 4];
        As_t[aq0 * 4 + 0][ar0] = v0.x;  As_t[aq0 * 4 + 1][ar0] = v0.y;
        As_t[aq0 * 4 + 2][ar0] = v0.z;  As_t[aq0 * 4 + 3][ar0] = v0.w;
        As_t[aq1 * 4 + 0][ar1] = v1.x;  As_t[aq1 * 4 + 1][ar1] = v1.y;
        As_t[aq1 * 4 + 2][ar1] = v1.z;  As_t[aq1 * 4 + 3][ar1] = v1.w;
        As_t[aq2 * 4 + 0][ar2] = v2.x;  As_t[aq2 * 4 + 1][ar2] = v2.y;
        As_t[aq2 * 4 + 2][ar2] = v2.z;  As_t[aq2 * 4 + 3][ar2] = v2.w;
        As_t[aq3 * 4 + 0][ar3] = v3.x;  As_t[aq3 * 4 + 1][ar3] = v3.y;
        As_t[aq3 * 4 + 2][ar3] = v3.z;  As_t[aq3 * 4 + 3][ar3] = v3.w;
        *(float4*)&Ws[wk0][wq0 * 4] = *(const float4*)&W[wk0 * G4 + jc + wq0 * 4];
        *(float4*)&Ws[wk1][wq1 * 4] = *(const float4*)&W[wk1 * G4 + jc + wq1 * 4];
        *(float4*)&Ws[wk2][wq2 * 4] = *(const float4*)&W[wk2 * G4 + jc + wq2 * 4];
        *(float4*)&Ws[wk3][wq3 * 4] = *(const float4*)&W[wk3 * G4 + jc + wq3 * 4];
    }
    __syncthreads();

    int T = KMAIN >> 6;
    for (int ti = 0; ti < T; ti++) {
        int kn = (ti + 1) << 6;
        bool have = (ti + 1 < T);
        float4 pa0, pa1, pa2, pa3, pw0, pw1, pw2, pw3;
        float pe[16];
        // ---- prefetch tile ti+1 into registers ----
        if (have) {
            if (kn < 256) {
                pa0 = *(const float4*)&h_in[(rb + ar0) * 256 + kn + aq0 * 4];
                pa1 = *(const float4*)&h_in[(rb + ar1) * 256 + kn + aq1 * 4];
                pa2 = *(const float4*)&h_in[(rb + ar2) * 256 + kn + aq2 * 4];
                pa3 = *(const float4*)&h_in[(rb + ar3) * 256 + kn + aq3 * 4];
            } else {
                #pragma unroll
                for (int l = 0; l < 16; l++) {
                    int idx = tid + l * 128;
                    int k = idx & 63, r = idx >> 6;
                    pe[l] = g_ext[(rb + r) * 257 + (kn - 256 + k)];
                }
            }
            pw0 = *(const float4*)&W[(kn + wk0) * G4 + jc + wq0 * 4];
            pw1 = *(const float4*)&W[(kn + wk1) * G4 + jc + wq1 * 4];
            pw2 = *(const float4*)&W[(kn + wk2) * G4 + jc + wq2 * 4];
            pw3 = *(const float4*)&W[(kn + wk3) * G4 + jc + wq3 * 4];
        }

        // ---- compute: 8 sub-chunks of 8, FFMA temp + Kahan fold ----
        #pragma unroll
        for (int k8 = 0; k8 < 8; k8++) {
            float tmp[2][4] = {};
            #pragma unroll
            for (int kk = 0; kk < 8; kk++) {
                int k = k8 * 8 + kk;
                float4 w = *(const float4*)&Ws[k][tx * 4];
                float2 a = *(const float2*)&As_t[k][ty * 2];
                tmp[0][0] = fmaf(a.x, w.x, tmp[0][0]);
                tmp[0][1] = fmaf(a.x, w.y, tmp[0][1]);
                tmp[0][2] = fmaf(a.x, w.z, tmp[0][2]);
                tmp[0][3] = fmaf(a.x, w.w, tmp[0][3]);
                tmp[1][0] = fmaf(a.y, w.x, tmp[1][0]);
                tmp[1][1] = fmaf(a.y, w.y, tmp[1][1]);
                tmp[1][2] = fmaf(a.y, w.z, tmp[1][2]);
                tmp[1][3] = fmaf(a.y, w.w, tmp[1][3]);
            }
            #pragma unroll
            for (int r = 0; r < 2; r++)
                #pragma unroll
                for (int cq = 0; cq < 4; cq++)
                    KAHAN_ADD(acc[r][cq], cmp[r][cq], tmp[r][cq]);
        }
        __syncthreads();

        // ---- store prefetched registers into smem ----
        if (have) {
            if (kn < 256) {
                As_t[aq0 * 4 + 0][ar0] = pa0.x;  As_t[aq0 * 4 + 1][ar0] = pa0.y;
                As_t[aq0 * 4 + 2][ar0] = pa0.z;  As_t[aq0 * 4 + 3][ar0] = pa0.w;
                As_t[aq1 * 4 + 0][ar1] = pa1.x;  As_t[aq1 * 4 + 1][ar1] = pa1.y;
                As_t[aq1 * 4 + 2][ar1] = pa1.z;  As_t[aq1 * 4 + 3][ar1] = pa1.w;
                As_t[aq2 * 4 + 0][ar2] = pa2.x;  As_t[aq2 * 4 + 1][ar2] = pa2.y;
                As_t[aq2 * 4 + 2][ar2] = pa2.z;  As_t[aq2 * 4 + 3][ar2] = pa2.w;
                As_t[aq3 * 4 + 0][ar3] = pa3.x;  As_t[aq3 * 4 + 1][ar3] = pa3.y;
                As_t[aq3 * 4 + 2][ar3] = pa3.z;  As_t[aq3 * 4 + 3][ar3] = pa3.w;
            } else {
                #pragma unroll
                for (int l = 0; l < 16; l++) {
                    int idx = tid + l * 128;
                    int k = idx & 63, r = idx >> 6;
                    As_t[k][r] = pe[l];
                }
            }
            *(float4*)&Ws[wk0][wq0 * 4] = pw0;
            *(float4*)&Ws[wk1][wq1 * 4] = pw1;
            *(float4*)&Ws[wk2][wq2 * 4] = pw2;
            *(float4*)&Ws[wk3][wq3 * 4] = pw3;
            __syncthreads();
        }
    }

    // ---- final scalar input column (x_t for enc, dec_in for dec) ----
    int jb = jc + tx * 4;
    float4 wlast = *(const float4*)&W[KMAIN * G4 + jb];
    #pragma unroll
    for (int r = 0; r < 2; r++) {
        int b = rb + ty * 2 + r;
        float e = is_enc ? xptr[b * S + t] : g_ext[b * 257 + 256];
        KAHAN_ADD(acc[r][0], cmp[r][0], e * wlast.x);
        KAHAN_ADD(acc[r][1], cmp[r][1], e * wlast.y);
        KAHAN_ADD(acc[r][2], cmp[r][2], e * wlast.z);
        KAHAN_ADD(acc[r][3], cmp[r][3], e * wlast.w);
    }

    int unit = (jc >> 2) + tx;
    float bi = bias[jb + 0], bf = bias[jb + 1], bg = bias[jb + 2], bo = bias[jb + 3];
    #pragma unroll
    for (int r = 0; r < 2; r++) {
        int b = rb + ty * 2 + r;
        float iv = sig_xla(acc[r][0] + bi);
        float fv = sig_xla(acc[r][1] + bf);
        float gv = tanh_xla(acc[r][2] + bg);
        float ov = sig_xla(acc[r][3] + bo);
        float cold = g_c[b * H + unit];
        float cn = fv * cold + iv * gv;
        float hh = ov * tanh_xla(cn);
        g_c[b * H + unit] = cn;
        h_out[b * H + unit] = hh;
        if (is_enc) g_enc_out[b * (S * H) + t * H + unit] = hh;
    }
}

// ---------------- encW1 precompute: [b][u][s] = enc_out[b,s,:] . W1[u,:] ----
__global__ __launch_bounds__(256) void encW1_kernel(const float* __restrict__ W1)
{
    int w = blockIdx.x * 8 + (threadIdx.x >> 5);
    int lane = threadIdx.x & 31;
    int b = w >> 8, s = w & 255;
    const float* e = g_enc_out + b * (S * H) + s * H;
    float ev[8];
    #pragma unroll
    for (int i = 0; i < 8; i++) ev[i] = e[lane + 32 * i];
    #pragma unroll
    for (int u = 0; u < U; u++) {
        float p = 0.f, c = 0.f;
        #pragma unroll
        for (int i = 0; i < 8; i++) KAHAN_ADD(p, c, ev[i] * W1[u * 256 + lane + 32 * i]);
        #pragma unroll
        for (int o = 16; o; o >>= 1) p += __shfl_xor_sync(0xffffffffu, p, o);
        if (lane == 0) g_encW1[b * (U * S) + u * S + s] = p;
    }
}

// ---------------- fused attention step (R9 exact) ---------------------------
__global__ __launch_bounds__(256) void attn_step(const float* __restrict__ x,
                                                 const void* __restrict__ yv,
                                                 const float* __restrict__ W2,
                                                 const float* __restrict__ V,
                                                 float* __restrict__ outp,
                                                 int t, int parity)
{
    const float* h_in = parity ? g_hB : g_hA;
    int b = blockIdx.x, tid = threadIdx.x;

    __shared__ float sh_h[256];
    __shared__ float sh_w2h[16];
    __shared__ float sV[16];
    __shared__ float sh_log[256];
    __shared__ float sh_aj[256];
    __shared__ float sh_red[256];
    __shared__ int   sh_idx[256];
    __shared__ float sgp[8][256];

    sh_h[tid] = h_in[b * H + tid];
    if (tid == 0) g_ext[b * 257 + 256] = g_decnext[b];
    if (tid < U)  sV[tid] = V[tid];
    __syncthreads();

    int wid = tid >> 5, lane = tid & 31;
    for (int u = wid; u < U; u += 8) {
        float p = 0.f, c = 0.f;
        #pragma unroll
        for (int k = lane; k < 256; k += 32) KAHAN_ADD(p, c, sh_h[k] * W2[u * 256 + k]);
        #pragma unroll
        for (int o = 16; o; o >>= 1) p += __shfl_xor_sync(0xffffffffu, p, o);
        if (lane == 0) sh_w2h[u] = p;
    }
    __syncthreads();

    const float* ew = g_encW1 + b * (U * S) + tid;
    float lg = 0.f, lgc = 0.f;
    #pragma unroll
    for (int u = 0; u < U; u++)
        KAHAN_ADD(lg, lgc, sV[u] * tanh_xla(ew[u * S] + sh_w2h[u]));
    sh_log[tid] = lg;
    sh_red[tid] = lg;
    sh_idx[tid] = tid;
    __syncthreads();

    // argmax (first occurrence on ties, matching jnp.argmax)
    #pragma unroll
    for (int off = 128; off; off >>= 1) {
        if (tid < off) {
            float ov = sh_red[tid + off]; int oi = sh_idx[tid + off];
            float cv = sh_red[tid];       int ci = sh_idx[tid];
            if (ov > cv || (ov == cv && oi < ci)) { sh_red[tid] = ov; sh_idx[tid] = oi; }
        }
        __syncthreads();
    }
    float mx = sh_red[0]; int mi = sh_idx[0];
    __syncthreads();

    float p = exp_p(lg - mx);
    sh_red[tid] = p;
    __syncthreads();
    #pragma unroll
    for (int off = 128; off; off >>= 1) {
        if (tid < off) sh_red[tid] += sh_red[tid + off];
        __syncthreads();
    }
    float sum = sh_red[0];
    sh_aj[tid] = __fdiv_rn(p, sum);

    if (tid == 0) {
        int yi = g_y64 ? (int)((const long long*)yv)[b * S + t]
                       : ((const int*)yv)[b * S + t];
        float logpy = sh_log[yi] - mx - (float)log((double)sum);
        g_lossbuf[t * B + b] = -logpy;
        outp[t * B + b] = (float)mi;
        g_decnext[b] = x[b * S + yi];
    }
    __syncthreads();

    // di[b][h] = sum_s aj[s] * enc_out[b][s][h]
    {
        int hc = tid & 31;
        int sg = tid >> 5;
        const float* eb = g_enc_out + (size_t)b * (S * H) + hc * 8;
        float a[8] = {}, cc[8] = {};
        int sbase = sg * 32;
        bool persist = (b < B_PERSIST);
        #pragma unroll
        for (int c8 = 0; c8 < 4; c8++) {
            float tmp[8] = {};
            #pragma unroll
            for (int kk = 0; kk < 8; kk++) {
                int s2 = sbase + c8 * 8 + kk;
                float e[8];
                if (persist) ld8_last(eb + (size_t)s2 * H, e);
                else         ld8_first(eb + (size_t)s2 * H, e);
                float aw = sh_aj[s2];
                #pragma unroll
                for (int j = 0; j < 8; j++) tmp[j] = fmaf(aw, e[j], tmp[j]);
            }
            #pragma unroll
            for (int j = 0; j < 8; j++) KAHAN_ADD(a[j], cc[j], tmp[j]);
        }
        #pragma unroll
        for (int j = 0; j < 8; j++) sgp[sg][hc * 8 + j] = a[j];
    }
    __syncthreads();
    {
        float a = sgp[0][tid], c = 0.f;
        #pragma unroll
        for (int g = 1; g < 8; g++) KAHAN_ADD(a, c, sgp[g][tid]);
        g_ext[b * 257 + tid] = a;
    }
}

// ---------------- deterministic loss reduction ------------------------------
__global__ void loss_reduce(float* __restrict__ outp, int do_write)
{
    __shared__ float sr[256];
    int tid = threadIdx.x;
    float a = 0.f, c = 0.f;
    for (int i = tid; i < S * B; i += 256) KAHAN_ADD(a, c, g_lossbuf[i]);
    sr[tid] = a;
    __syncthreads();
    #pragma unroll
    for (int off = 128; off; off >>= 1) {
        if (tid < off) sr[tid] += sr[tid + off];
        __syncthreads();
    }
    if (tid == 0 && do_write) outp[S * B] = __fdiv_rn(sr[0], 512.f * 512.f);
}

// ---------------- host launch ----------------------------------------------
extern "C" void kernel_launch(void* const* d_in, const int* in_sizes, int n_in,
                              void* d_out, int out_size)
{
    const float* x    = (const float*)d_in[0];
    const void*  y    = d_in[1];
    const float* eWih = (const float*)d_in[2];
    const float* eWhh = (const float*)d_in[3];
    const float* ebih = (const float*)d_in[4];
    const float* ebhh = (const float*)d_in[5];
    const float* dWih = (const float*)d_in[6];
    const float* dWhh = (const float*)d_in[7];
    const float* dbih = (const float*)d_in[8];
    const float* dbhh = (const float*)d_in[9];
    const float* W1   = (const float*)d_in[10];
    const float* W2   = (const float*)d_in[11];
    const float* V    = (const float*)d_in[12];
    float* outp = (float*)d_out;

    prep_kernel<<<(513 * G4 + 255) / 256, 256>>>(eWih, eWhh, ebih, ebhh,
                                                 dWih, dWhh, dbih, dbhh);
    init_kernel<<<(B * H + 255) / 256, 256>>>();
    detect_y<<<1, 1>>>(y);

    dim3 grid(G4 / 32, B / 32);   // 32 x 16 = 512 CTAs

    // encoder (KMAIN=256, x_t handled in epilogue)
    for (int t = 0; t < S; t++)
        lstm_step<<<grid, 128>>>(x, 256, 1, t, t & 1);

    encW1_kernel<<<B * S / 8, 256>>>(W1);

    // decoder (KMAIN=512, dec_in handled in epilogue).
    // t = S-1 lstm output is unused by the reference -> skip it.
    for (int t = 0; t < S; t++) {
        attn_step<<<B, 256>>>(x, y, W2, V, outp, t, t & 1);
        if (t < S - 1) lstm_step<<<grid, 128>>>(x, 512, 0, t, t & 1);
    }

    loss_reduce<<<1, 256>>>(outp, out_size > S * B ? 1 : 0);
}

// round 15
// speedup vs baseline: 1.2506x; 1.2506x over previous
#include <cuda_runtime.h>
#include <math.h>

#define B 512
#define S 256
#define H 256
#define U 10
#define G4 1024   // 4*H
#define B_PERSIST 384   // batches whose enc_out slice is held L2-resident (96 MB)

// ---------------- device scratch (static allocations only) ----------------
__device__ float g_enc_out[B * S * H];   // [b][s][h]  134 MB
__device__ float g_encW1[B * U * S];     // [b][u][s]  5 MB
__device__ float g_Wenc[257 * G4];       // interleaved gate cols
__device__ float g_Wdec[513 * G4];
__device__ float g_bias_enc[G4];
__device__ float g_bias_dec[G4];
__device__ float g_hA[B * H];
__device__ float g_hB[B * H];
__device__ float g_c[B * H];
__device__ float g_ext[B * 257];         // decoder lstm extra input: [di(256) | dec_in(1)]
__device__ float g_decnext[B];           // staged teacher-forced input
__device__ float g_lossbuf[S * B];
__device__ int   g_y64;

// ---------------- 256-bit L2 eviction-priority loads ------------------------
__device__ __forceinline__ void ld8_last(const float* p, float f[8])
{
    unsigned long long q0, q1, q2, q3;
    asm volatile("ld.global.nc.L2::evict_last.v4.b64 {%0,%1,%2,%3}, [%4];"
                 : "=l"(q0), "=l"(q1), "=l"(q2), "=l"(q3) : "l"(p));
    f[0] = __uint_as_float((unsigned)q0); f[1] = __uint_as_float((unsigned)(q0 >> 32));
    f[2] = __uint_as_float((unsigned)q1); f[3] = __uint_as_float((unsigned)(q1 >> 32));
    f[4] = __uint_as_float((unsigned)q2); f[5] = __uint_as_float((unsigned)(q2 >> 32));
    f[6] = __uint_as_float((unsigned)q3); f[7] = __uint_as_float((unsigned)(q3 >> 32));
}
__device__ __forceinline__ void ld8_first(const float* p, float f[8])
{
    unsigned long long q0, q1, q2, q3;
    asm volatile("ld.global.nc.L2::evict_first.v4.b64 {%0,%1,%2,%3}, [%4];"
                 : "=l"(q0), "=l"(q1), "=l"(q2), "=l"(q3) : "l"(p));
    f[0] = __uint_as_float((unsigned)q0); f[1] = __uint_as_float((unsigned)(q0 >> 32));
    f[2] = __uint_as_float((unsigned)q1); f[3] = __uint_as_float((unsigned)(q1 >> 32));
    f[4] = __uint_as_float((unsigned)q2); f[5] = __uint_as_float((unsigned)(q2 >> 32));
    f[6] = __uint_as_float((unsigned)q3); f[7] = __uint_as_float((unsigned)(q3 >> 32));
}

// ---------------- XLA-matching transcendentals -----------------------------
__device__ __forceinline__ float exp_p(float x)
{
    x = fminf(fmaxf(x, -87.0f), 87.0f);
    float t = fmaf(x, 1.44269504088896341f, 12582912.0f);
    float n = t - 12582912.0f;
    float r = fmaf(n, -0.693359375f, x);
    r = fmaf(n, 2.12194440e-4f, r);
    float p = 1.9875691500e-4f;
    p = fmaf(p, r, 1.3981999507e-3f);
    p = fmaf(p, r, 8.3334519073e-3f);
    p = fmaf(p, r, 4.1665795894e-2f);
    p = fmaf(p, r, 1.6666665459e-1f);
    p = fmaf(p, r, 5.0000001201e-1f);
    float res = fmaf(r * r, p, r) + 1.0f;
    int i = (int)n;
    float scale = __int_as_float((i + 127) << 23);
    return res * scale;
}

__device__ __forceinline__ float tanh_xla(float x)
{
    if (fabsf(x) < 0.0004f) return x;
    float xc = fminf(fmaxf(x, -7.90531110763549805f), 7.90531110763549805f);
    float x2 = xc * xc;
    float np = fmaf(x2, -2.76076847742355e-16f, 2.00018790482477e-13f);
    np = fmaf(x2, np, -8.60467152213735e-11f);
    np = fmaf(x2, np, 5.12229709037114e-08f);
    np = fmaf(x2, np, 1.48572235717979e-05f);
    np = fmaf(x2, np, 6.37261928875436e-04f);
    np = fmaf(x2, np, 4.89352455891786e-03f);
    np = np * xc;
    float dp = fmaf(x2, 1.19825839466702e-06f, 1.18534705686654e-04f);
    dp = fmaf(x2, dp, 2.26843463243900e-03f);
    dp = fmaf(x2, dp, 4.89352518554385e-03f);
    return __fdiv_rn(np, dp);
}

__device__ __forceinline__ float sig_xla(float x)
{
    return fmaf(0.5f, tanh_xla(0.5f * x), 0.5f);
}

#define KAHAN_ADD(acc, comp, val)            \
    do {                                     \
        float _y = (val) - (comp);           \
        float _t = (acc) + _y;               \
        (comp) = (_t - (acc)) - _y;          \
        (acc) = _t;                          \
    } while (0)

// ---------------- weight prep: interleave gate columns --------------------
__global__ void prep_kernel(const float* __restrict__ eWih, const float* __restrict__ eWhh,
                            const float* __restrict__ ebih, const float* __restrict__ ebhh,
                            const float* __restrict__ dWih, const float* __restrict__ dWhh,
                            const float* __restrict__ dbih, const float* __restrict__ dbhh)
{
    int idx = blockIdx.x * blockDim.x + threadIdx.x;
    if (idx >= 513 * G4) return;
    int k = idx >> 10, j = idx & 1023;
    int h = j >> 2, g = j & 3;
    int r = g * 256 + h;
    float wd = (k < 256) ? dWhh[r * 256 + k] : dWih[r * 257 + (k - 256)];
    g_Wdec[idx] = wd;
    if (k < 257) {
        float we = (k < 256) ? eWhh[r * 256 + k] : eWih[r];
        g_Wenc[idx] = we;
    }
    if (k == 0) {
        g_bias_enc[j] = ebih[r] + ebhh[r];
        g_bias_dec[j] = dbih[r] + dbhh[r];
    }
}

__global__ void init_kernel()
{
    int idx = blockIdx.x * blockDim.x + threadIdx.x;
    if (idx < B * H) { g_hA[idx] = 0.f; g_c[idx] = 0.f; }
    if (idx < B)     { g_decnext[idx] = 0.f; }
}

__global__ void detect_y(const void* __restrict__ y)
{
    const int* yi = (const int*)y;
    int all0 = 1;
    for (int i = 1; i < 64; i += 2) if (yi[i] != 0) all0 = 0;
    g_y64 = all0;
}

// ---------------- fused GEMM + LSTM pointwise step -------------------------
// 32x64 tile, 256 threads, 2x4 microtile, register-prefetch pipeline.
// __launch_bounds__(256, 3): cap regs (~85) so 3 CTAs fit per SM.
// Per-output k-summation order identical to R9 (bitwise-same numerics).
__global__ __launch_bounds__(256, 3) void lstm_step(const float* __restrict__ xptr,
                                                    int KMAIN, int is_enc, int t, int parity)
{
    const float* h_in  = parity ? g_hB : g_hA;
    float*       h_out = parity ? g_hA : g_hB;
    const float* W     = is_enc ? g_Wenc : g_Wdec;
    const float* bias  = is_enc ? g_bias_enc : g_bias_dec;

    __shared__ float As_t[64][34];   // [k][row], 32 rows padded to 34
    __shared__ float Ws[64][64];

    int rb = blockIdx.y * 32, jc = blockIdx.x * 64;
    int tid = threadIdx.x;
    int tx = tid & 15, ty = tid >> 4;       // ty 0..15 -> rows ty*2, ty*2+1

    // loader indices
    int ar0 = tid >> 4,          aq0 = tid & 15;          // A h-region, 2 float4/thread
    int ar1 = (tid + 256) >> 4,  aq1 = (tid + 256) & 15;
    int wk0 = tid >> 4,          wq0 = tid & 15;          // W, 4 float4/thread
    int wk1 = (tid + 256) >> 4,  wq1 = (tid + 256) & 15;
    int wk2 = (tid + 512) >> 4,  wq2 = (tid + 512) & 15;
    int wk3 = (tid + 768) >> 4,  wq3 = (tid + 768) & 15;

    float acc[2][4] = {};
    float cmp[2][4] = {};

    // ---- load tile 0 (always h region) ----
    {
        float4 v0 = *(const float4*)&h_in[(rb + ar0) * 256 + aq0 * 4];
        float4 v1 = *(const float4*)&h_in[(rb + ar1) * 256 + aq1 * 4];
        As_t[aq0 * 4 + 0][ar0] = v0.x;  As_t[aq0 * 4 + 1][ar0] = v0.y;
        As_t[aq0 * 4 + 2][ar0] = v0.z;  As_t[aq0 * 4 + 3][ar0] = v0.w;
        As_t[aq1 * 4 + 0][ar1] = v1.x;  As_t[aq1 * 4 + 1][ar1] = v1.y;
        As_t[aq1 * 4 + 2][ar1] = v1.z;  As_t[aq1 * 4 + 3][ar1] = v1.w;
        *(float4*)&Ws[wk0][wq0 * 4] = *(const float4*)&W[wk0 * G4 + jc + wq0 * 4];
        *(float4*)&Ws[wk1][wq1 * 4] = *(const float4*)&W[wk1 * G4 + jc + wq1 * 4];
        *(float4*)&Ws[wk2][wq2 * 4] = *(const float4*)&W[wk2 * G4 + jc + wq2 * 4];
        *(float4*)&Ws[wk3][wq3 * 4] = *(const float4*)&W[wk3 * G4 + jc + wq3 * 4];
    }
    __syncthreads();

    int T = KMAIN >> 6;
    for (int ti = 0; ti < T; ti++) {
        int kn = (ti + 1) << 6;
        bool have = (ti + 1 < T);
        float4 pa0, pa1, pw0, pw1, pw2, pw3;
        float pe[8];
        // ---- prefetch tile ti+1 into registers ----
        if (have) {
            if (kn < 256) {
                pa0 = *(const float4*)&h_in[(rb + ar0) * 256 + kn + aq0 * 4];
                pa1 = *(const float4*)&h_in[(rb + ar1) * 256 + kn + aq1 * 4];
            } else {
                #pragma unroll
                for (int l = 0; l < 8; l++) {
                    int idx = tid + l * 256;
                    int k = idx & 63, r = idx >> 6;
                    pe[l] = g_ext[(rb + r) * 257 + (kn - 256 + k)];
                }
            }
            pw0 = *(const float4*)&W[(kn + wk0) * G4 + jc + wq0 * 4];
            pw1 = *(const float4*)&W[(kn + wk1) * G4 + jc + wq1 * 4];
            pw2 = *(const float4*)&W[(kn + wk2) * G4 + jc + wq2 * 4];
            pw3 = *(const float4*)&W[(kn + wk3) * G4 + jc + wq3 * 4];
        }

        // ---- compute: 8 sub-chunks of 8, FFMA temp + Kahan fold ----
        #pragma unroll
        for (int k8 = 0; k8 < 8; k8++) {
            float tmp[2][4] = {};
            #pragma unroll
            for (int kk = 0; kk < 8; kk++) {
                int k = k8 * 8 + kk;
                float4 w = *(const float4*)&Ws[k][tx * 4];
                float2 a = *(const float2*)&As_t[k][ty * 2];
                tmp[0][0] = fmaf(a.x, w.x, tmp[0][0]);
                tmp[0][1] = fmaf(a.x, w.y, tmp[0][1]);
                tmp[0][2] = fmaf(a.x, w.z, tmp[0][2]);
                tmp[0][3] = fmaf(a.x, w.w, tmp[0][3]);
                tmp[1][0] = fmaf(a.y, w.x, tmp[1][0]);
                tmp[1][1] = fmaf(a.y, w.y, tmp[1][1]);
                tmp[1][2] = fmaf(a.y, w.z, tmp[1][2]);
                tmp[1][3] = fmaf(a.y, w.w, tmp[1][3]);
            }
            #pragma unroll
            for (int r = 0; r < 2; r++)
                #pragma unroll
                for (int cq = 0; cq < 4; cq++)
                    KAHAN_ADD(acc[r][cq], cmp[r][cq], tmp[r][cq]);
        }
        __syncthreads();

        // ---- store prefetched registers into smem ----
        if (have) {
            if (kn < 256) {
                As_t[aq0 * 4 + 0][ar0] = pa0.x;  As_t[aq0 * 4 + 1][ar0] = pa0.y;
                As_t[aq0 * 4 + 2][ar0] = pa0.z;  As_t[aq0 * 4 + 3][ar0] = pa0.w;
                As_t[aq1 * 4 + 0][ar1] = pa1.x;  As_t[aq1 * 4 + 1][ar1] = pa1.y;
                As_t[aq1 * 4 + 2][ar1] = pa1.z;  As_t[aq1 * 4 + 3][ar1] = pa1.w;
            } else {
                #pragma unroll
                for (int l = 0; l < 8; l++) {
                    int idx = tid + l * 256;
                    int k = idx & 63, r = idx >> 6;
                    As_t[k][r] = pe[l];
                }
            }
            *(float4*)&Ws[wk0][wq0 * 4] = pw0;
            *(float4*)&Ws[wk1][wq1 * 4] = pw1;
            *(float4*)&Ws[wk2][wq2 * 4] = pw2;
            *(float4*)&Ws[wk3][wq3 * 4] = pw3;
            __syncthreads();
        }
    }

    // ---- final scalar input column (x_t for enc, dec_in for dec) ----
    int jb = jc + tx * 4;
    float4 wlast = *(const float4*)&W[KMAIN * G4 + jb];
    #pragma unroll
    for (int r = 0; r < 2; r++) {
        int b = rb + ty * 2 + r;
        float e = is_enc ? xptr[b * S + t] : g_ext[b * 257 + 256];
        KAHAN_ADD(acc[r][0], cmp[r][0], e * wlast.x);
        KAHAN_ADD(acc[r][1], cmp[r][1], e * wlast.y);
        KAHAN_ADD(acc[r][2], cmp[r][2], e * wlast.z);
        KAHAN_ADD(acc[r][3], cmp[r][3], e * wlast.w);
    }

    int unit = (jc >> 2) + tx;
    float bi = bias[jb + 0], bf = bias[jb + 1], bg = bias[jb + 2], bo = bias[jb + 3];
    #pragma unroll
    for (int r = 0; r < 2; r++) {
        int b = rb + ty * 2 + r;
        float iv = sig_xla(acc[r][0] + bi);
        float fv = sig_xla(acc[r][1] + bf);
        float gv = tanh_xla(acc[r][2] + bg);
        float ov = sig_xla(acc[r][3] + bo);
        float cold = g_c[b * H + unit];
        float cn = fv * cold + iv * gv;
        float hh = ov * tanh_xla(cn);
        g_c[b * H + unit] = cn;
        h_out[b * H + unit] = hh;
        if (is_enc) g_enc_out[b * (S * H) + t * H + unit] = hh;
    }
}

// ---------------- encW1 precompute: [b][u][s] = enc_out[b,s,:] . W1[u,:] ----
__global__ __launch_bounds__(256) void encW1_kernel(const float* __restrict__ W1)
{
    int w = blockIdx.x * 8 + (threadIdx.x >> 5);
    int lane = threadIdx.x & 31;
    int b = w >> 8, s = w & 255;
    const float* e = g_enc_out + b * (S * H) + s * H;
    float ev[8];
    #pragma unroll
    for (int i = 0; i < 8; i++) ev[i] = e[lane + 32 * i];
    #pragma unroll
    for (int u = 0; u < U; u++) {
        float p = 0.f, c = 0.f;
        #pragma unroll
        for (int i = 0; i < 8; i++) KAHAN_ADD(p, c, ev[i] * W1[u * 256 + lane + 32 * i]);
        #pragma unroll
        for (int o = 16; o; o >>= 1) p += __shfl_xor_sync(0xffffffffu, p, o);
        if (lane == 0) g_encW1[b * (U * S) + u * S + s] = p;
    }
}

// ---------------- fused attention step (R9 exact) ---------------------------
__global__ __launch_bounds__(256) void attn_step(const float* __restrict__ x,
                                                 const void* __restrict__ yv,
                                                 const float* __restrict__ W2,
                                                 const float* __restrict__ V,
                                                 float* __restrict__ outp,
                                                 int t, int parity)
{
    const float* h_in = parity ? g_hB : g_hA;
    int b = blockIdx.x, tid = threadIdx.x;

    __shared__ float sh_h[256];
    __shared__ float sh_w2h[16];
    __shared__ float sV[16];
    __shared__ float sh_log[256];
    __shared__ float sh_aj[256];
    __shared__ float sh_red[256];
    __shared__ int   sh_idx[256];
    __shared__ float sgp[8][256];

    sh_h[tid] = h_in[b * H + tid];
    if (tid == 0) g_ext[b * 257 + 256] = g_decnext[b];
    if (tid < U)  sV[tid] = V[tid];
    __syncthreads();

    int wid = tid >> 5, lane = tid & 31;
    for (int u = wid; u < U; u += 8) {
        float p = 0.f, c = 0.f;
        #pragma unroll
        for (int k = lane; k < 256; k += 32) KAHAN_ADD(p, c, sh_h[k] * W2[u * 256 + k]);
        #pragma unroll
        for (int o = 16; o; o >>= 1) p += __shfl_xor_sync(0xffffffffu, p, o);
        if (lane == 0) sh_w2h[u] = p;
    }
    __syncthreads();

    const float* ew = g_encW1 + b * (U * S) + tid;
    float lg = 0.f, lgc = 0.f;
    #pragma unroll
    for (int u = 0; u < U; u++)
        KAHAN_ADD(lg, lgc, sV[u] * tanh_xla(ew[u * S] + sh_w2h[u]));
    sh_log[tid] = lg;
    sh_red[tid] = lg;
    sh_idx[tid] = tid;
    __syncthreads();

    // argmax (first occurrence on ties, matching jnp.argmax)
    #pragma unroll
    for (int off = 128; off; off >>= 1) {
        if (tid < off) {
            float ov = sh_red[tid + off]; int oi = sh_idx[tid + off];
            float cv = sh_red[tid];       int ci = sh_idx[tid];
            if (ov > cv || (ov == cv && oi < ci)) { sh_red[tid] = ov; sh_idx[tid] = oi; }
        }
        __syncthreads();
    }
    float mx = sh_red[0]; int mi = sh_idx[0];
    __syncthreads();

    float p = exp_p(lg - mx);
    sh_red[tid] = p;
    __syncthreads();
    #pragma unroll
    for (int off = 128; off; off >>= 1) {
        if (tid < off) sh_red[tid] += sh_red[tid + off];
        __syncthreads();
    }
    float sum = sh_red[0];
    sh_aj[tid] = __fdiv_rn(p, sum);

    if (tid == 0) {
        int yi = g_y64 ? (int)((const long long*)yv)[b * S + t]
                       : ((const int*)yv)[b * S + t];
        float logpy = sh_log[yi] - mx - (float)log((double)sum);
        g_lossbuf[t * B + b] = -logpy;
        outp[t * B + b] = (float)mi;
        g_decnext[b] = x[b * S + yi];
    }
    __syncthreads();

    // di[b][h] = sum_s aj[s] * enc_out[b][s][h]
    {
        int hc = tid & 31;
        int sg = tid >> 5;
        const float* eb = g_enc_out + (size_t)b * (S * H) + hc * 8;
        float a[8] = {}, cc[8] = {};
        int sbase = sg * 32;
        bool persist = (b < B_PERSIST);
        #pragma unroll
        for (int c8 = 0; c8 < 4; c8++) {
            float tmp[8] = {};
            #pragma unroll
            for (int kk = 0; kk < 8; kk++) {
                int s2 = sbase + c8 * 8 + kk;
                float e[8];
                if (persist) ld8_last(eb + (size_t)s2 * H, e);
                else         ld8_first(eb + (size_t)s2 * H, e);
                float aw = sh_aj[s2];
                #pragma unroll
                for (int j = 0; j < 8; j++) tmp[j] = fmaf(aw, e[j], tmp[j]);
            }
            #pragma unroll
            for (int j = 0; j < 8; j++) KAHAN_ADD(a[j], cc[j], tmp[j]);
        }
        #pragma unroll
        for (int j = 0; j < 8; j++) sgp[sg][hc * 8 + j] = a[j];
    }
    __syncthreads();
    {
        float a = sgp[0][tid], c = 0.f;
        #pragma unroll
        for (int g = 1; g < 8; g++) KAHAN_ADD(a, c, sgp[g][tid]);
        g_ext[b * 257 + tid] = a;
    }
}

// ---------------- deterministic loss reduction ------------------------------
__global__ void loss_reduce(float* __restrict__ outp, int do_write)
{
    __shared__ float sr[256];
    int tid = threadIdx.x;
    float a = 0.f, c = 0.f;
    for (int i = tid; i < S * B; i += 256) KAHAN_ADD(a, c, g_lossbuf[i]);
    sr[tid] = a;
    __syncthreads();
    #pragma unroll
    for (int off = 128; off; off >>= 1) {
        if (tid < off) sr[tid] += sr[tid + off];
        __syncthreads();
    }
    if (tid == 0 && do_write) outp[S * B] = __fdiv_rn(sr[0], 512.f * 512.f);
}

// ---------------- host launch ----------------------------------------------
extern "C" void kernel_launch(void* const* d_in, const int* in_sizes, int n_in,
                              void* d_out, int out_size)
{
    const float* x    = (const float*)d_in[0];
    const void*  y    = d_in[1];
    const float* eWih = (const float*)d_in[2];
    const float* eWhh = (const float*)d_in[3];
    const float* ebih = (const float*)d_in[4];
    const float* ebhh = (const float*)d_in[5];
    const float* dWih = (const float*)d_in[6];
    const float* dWhh = (const float*)d_in[7];
    const float* dbih = (const float*)d_in[8];
    const float* dbhh = (const float*)d_in[9];
    const float* W1   = (const float*)d_in[10];
    const float* W2   = (const float*)d_in[11];
    const float* V    = (const float*)d_in[12];
    float* outp = (float*)d_out;

    prep_kernel<<<(513 * G4 + 255) / 256, 256>>>(eWih, eWhh, ebih, ebhh,
                                                 dWih, dWhh, dbih, dbhh);
    init_kernel<<<(B * H + 255) / 256, 256>>>();
    detect_y<<<1, 1>>>(y);

    dim3 grid(G4 / 64, B / 32);   // 16 x 16 = 256 CTAs

    // encoder (KMAIN=256, x_t handled in epilogue)
    for (int t = 0; t < S; t++)
        lstm_step<<<grid, 256>>>(x, 256, 1, t, t & 1);

    encW1_kernel<<<B * S / 8, 256>>>(W1);

    // decoder (KMAIN=512, dec_in handled in epilogue).
    // t = S-1 lstm output is unused by the reference -> skip it.
    for (int t = 0; t < S; t++) {
        attn_step<<<B, 256>>>(x, y, W2, V, outp, t, t & 1);
        if (t < S - 1) lstm_step<<<grid, 256>>>(x, 512, 0, t, t & 1);
    }

    loss_reduce<<<1, 256>>>(outp, out_size > S * B ? 1 : 0);
}

// round 16
// speedup vs baseline: 1.3312x; 1.0644x over previous
#include <cuda_runtime.h>
#include <math.h>

#define B 512
#define S 256
#define H 256
#define U 10
#define G4 1024   // 4*H
#define B_PERSIST 384   // batches whose enc_out slice is held L2-resident (96 MB)

// ---------------- device scratch (static allocations only) ----------------
__device__ float g_enc_out[B * S * H];   // [b][s][h]  134 MB
__device__ float g_encW1[B * U * S];     // [b][u][s]  5 MB
__device__ float g_Wenc[257 * G4];       // interleaved gate cols
__device__ float g_Wdec[513 * G4];
__device__ float g_bias_enc[G4];
__device__ float g_bias_dec[G4];
__device__ float g_hA[B * H];
__device__ float g_hB[B * H];
__device__ float g_c[B * H];
__device__ float g_ext[B * 257];         // decoder lstm extra input: [di(256) | dec_in(1)]
__device__ float g_decnext[B];           // staged teacher-forced input
__device__ float g_lossbuf[S * B];
__device__ int   g_y64;

// ---------------- cp.async helpers ------------------------------------------
__device__ __forceinline__ void cpa16(void* dst_smem, const void* src_gmem)
{
    unsigned d = (unsigned)__cvta_generic_to_shared(dst_smem);
    asm volatile("cp.async.ca.shared.global [%0], [%1], 16;" :: "r"(d), "l"(src_gmem));
}
__device__ __forceinline__ void cpa4(void* dst_smem, const void* src_gmem)
{
    unsigned d = (unsigned)__cvta_generic_to_shared(dst_smem);
    asm volatile("cp.async.ca.shared.global [%0], [%1], 4;" :: "r"(d), "l"(src_gmem));
}
#define CPA_COMMIT() asm volatile("cp.async.commit_group;" ::: "memory")
#define CPA_WAIT1()  asm volatile("cp.async.wait_group 1;" ::: "memory")
#define CPA_WAIT0()  asm volatile("cp.async.wait_group 0;" ::: "memory")

// ---------------- 256-bit L2 eviction-priority loads ------------------------
__device__ __forceinline__ void ld8_last(const float* p, float f[8])
{
    unsigned long long q0, q1, q2, q3;
    asm volatile("ld.global.nc.L2::evict_last.v4.b64 {%0,%1,%2,%3}, [%4];"
                 : "=l"(q0), "=l"(q1), "=l"(q2), "=l"(q3) : "l"(p));
    f[0] = __uint_as_float((unsigned)q0); f[1] = __uint_as_float((unsigned)(q0 >> 32));
    f[2] = __uint_as_float((unsigned)q1); f[3] = __uint_as_float((unsigned)(q1 >> 32));
    f[4] = __uint_as_float((unsigned)q2); f[5] = __uint_as_float((unsigned)(q2 >> 32));
    f[6] = __uint_as_float((unsigned)q3); f[7] = __uint_as_float((unsigned)(q3 >> 32));
}
__device__ __forceinline__ void ld8_first(const float* p, float f[8])
{
    unsigned long long q0, q1, q2, q3;
    asm volatile("ld.global.nc.L2::evict_first.v4.b64 {%0,%1,%2,%3}, [%4];"
                 : "=l"(q0), "=l"(q1), "=l"(q2), "=l"(q3) : "l"(p));
    f[0] = __uint_as_float((unsigned)q0); f[1] = __uint_as_float((unsigned)(q0 >> 32));
    f[2] = __uint_as_float((unsigned)q1); f[3] = __uint_as_float((unsigned)(q1 >> 32));
    f[4] = __uint_as_float((unsigned)q2); f[5] = __uint_as_float((unsigned)(q2 >> 32));
    f[6] = __uint_as_float((unsigned)q3); f[7] = __uint_as_float((unsigned)(q3 >> 32));
}

// ---------------- XLA-matching transcendentals -----------------------------
__device__ __forceinline__ float exp_p(float x)
{
    x = fminf(fmaxf(x, -87.0f), 87.0f);
    float t = fmaf(x, 1.44269504088896341f, 12582912.0f);
    float n = t - 12582912.0f;
    float r = fmaf(n, -0.693359375f, x);
    r = fmaf(n, 2.12194440e-4f, r);
    float p = 1.9875691500e-4f;
    p = fmaf(p, r, 1.3981999507e-3f);
    p = fmaf(p, r, 8.3334519073e-3f);
    p = fmaf(p, r, 4.1665795894e-2f);
    p = fmaf(p, r, 1.6666665459e-1f);
    p = fmaf(p, r, 5.0000001201e-1f);
    float res = fmaf(r * r, p, r) + 1.0f;
    int i = (int)n;
    float scale = __int_as_float((i + 127) << 23);
    return res * scale;
}

__device__ __forceinline__ float tanh_xla(float x)
{
    if (fabsf(x) < 0.0004f) return x;
    float xc = fminf(fmaxf(x, -7.90531110763549805f), 7.90531110763549805f);
    float x2 = xc * xc;
    float np = fmaf(x2, -2.76076847742355e-16f, 2.00018790482477e-13f);
    np = fmaf(x2, np, -8.60467152213735e-11f);
    np = fmaf(x2, np, 5.12229709037114e-08f);
    np = fmaf(x2, np, 1.48572235717979e-05f);
    np = fmaf(x2, np, 6.37261928875436e-04f);
    np = fmaf(x2, np, 4.89352455891786e-03f);
    np = np * xc;
    float dp = fmaf(x2, 1.19825839466702e-06f, 1.18534705686654e-04f);
    dp = fmaf(x2, dp, 2.26843463243900e-03f);
    dp = fmaf(x2, dp, 4.89352518554385e-03f);
    return __fdiv_rn(np, dp);
}

__device__ __forceinline__ float sig_xla(float x)
{
    return fmaf(0.5f, tanh_xla(0.5f * x), 0.5f);
}

#define KAHAN_ADD(acc, comp, val)            \
    do {                                     \
        float _y = (val) - (comp);           \
        float _t = (acc) + _y;               \
        (comp) = (_t - (acc)) - _y;          \
        (acc) = _t;                          \
    } while (0)

// ---------------- weight prep: interleave gate columns --------------------
__global__ void prep_kernel(const float* __restrict__ eWih, const float* __restrict__ eWhh,
                            const float* __restrict__ ebih, const float* __restrict__ ebhh,
                            const float* __restrict__ dWih, const float* __restrict__ dWhh,
                            const float* __restrict__ dbih, const float* __restrict__ dbhh)
{
    int idx = blockIdx.x * blockDim.x + threadIdx.x;
    if (idx >= 513 * G4) return;
    int k = idx >> 10, j = idx & 1023;
    int h = j >> 2, g = j & 3;
    int r = g * 256 + h;
    float wd = (k < 256) ? dWhh[r * 256 + k] : dWih[r * 257 + (k - 256)];
    g_Wdec[idx] = wd;
    if (k < 257) {
        float we = (k < 256) ? eWhh[r * 256 + k] : eWih[r];
        g_Wenc[idx] = we;
    }
    if (k == 0) {
        g_bias_enc[j] = ebih[r] + ebhh[r];
        g_bias_dec[j] = dbih[r] + dbhh[r];
    }
}

__global__ void init_kernel()
{
    int idx = blockIdx.x * blockDim.x + threadIdx.x;
    if (idx < B * H) { g_hA[idx] = 0.f; g_c[idx] = 0.f; }
    if (idx < B)     { g_decnext[idx] = 0.f; }
}

__global__ void detect_y(const void* __restrict__ y)
{
    const int* yi = (const int*)y;
    int all0 = 1;
    for (int i = 1; i < 64; i += 2) if (yi[i] != 0) all0 = 0;
    g_y64 = all0;
}

// ---------------- fused GEMM + LSTM pointwise step -------------------------
// 32x64 tile, 256 threads, 2x4 microtile. k-tile 32, double-buffered smem,
// cp.async loads (no prefetch registers -> high occupancy).
// Flattened per-output MAC/fold order identical to R9 (bitwise-same).
__global__ __launch_bounds__(256) void lstm_step(const float* __restrict__ xptr,
                                                 int KMAIN, int is_enc, int t, int parity)
{
    const float* h_in  = parity ? g_hB : g_hA;
    float*       h_out = parity ? g_hA : g_hB;
    const float* W     = is_enc ? g_Wenc : g_Wdec;
    const float* bias  = is_enc ? g_bias_enc : g_bias_dec;

    __shared__ float Ab[2][32][36];   // [buf][row][k], row stride 36 (16B-aligned rows)
    __shared__ float Wb[2][32][64];   // [buf][k][j]

    int rb = blockIdx.y * 32, jc = blockIdx.x * 64;
    int tid = threadIdx.x;
    int tx = tid & 15, ty = tid >> 4;       // ty 0..15 -> rows ty*2, ty*2+1

    // loader indices
    int arow = tid >> 3, aq = tid & 7;          // A h-region: 1 float4/thread
    int wk0 = tid >> 4,           wq0 = tid & 15;   // W: 2 float4/thread
    int wk1 = (tid + 256) >> 4,   wq1 = (tid + 256) & 15;

    float acc[2][4] = {};
    float cmp[2][4] = {};

    // ---- issue tile 0 (always h region) ----
    cpa16(&Ab[0][arow][aq * 4], &h_in[(rb + arow) * 256 + aq * 4]);
    cpa16(&Wb[0][wk0][wq0 * 4], &W[wk0 * G4 + jc + wq0 * 4]);
    cpa16(&Wb[0][wk1][wq1 * 4], &W[wk1 * G4 + jc + wq1 * 4]);
    CPA_COMMIT();

    int T = KMAIN >> 5;
    for (int ti = 0; ti < T; ti++) {
        int kn = (ti + 1) << 5;
        bool have = (ti + 1 < T);
        int cb = ti & 1, nb = (ti + 1) & 1;

        // ---- issue tile ti+1 ----
        if (have) {
            if (kn < 256) {
                cpa16(&Ab[nb][arow][aq * 4], &h_in[(rb + arow) * 256 + kn + aq * 4]);
            } else {
                #pragma unroll
                for (int l = 0; l < 4; l++) {
                    int idx = tid + l * 256;
                    int k = idx & 31, r = idx >> 5;
                    cpa4(&Ab[nb][r][k], &g_ext[(rb + r) * 257 + (kn - 256) + k]);
                }
            }
            cpa16(&Wb[nb][wk0][wq0 * 4], &W[(kn + wk0) * G4 + jc + wq0 * 4]);
            cpa16(&Wb[nb][wk1][wq1 * 4], &W[(kn + wk1) * G4 + jc + wq1 * 4]);
            CPA_COMMIT();
            CPA_WAIT1();          // tile ti complete
        } else {
            CPA_WAIT0();
        }
        __syncthreads();

        // ---- compute: 4 sub-chunks of 8, FFMA temp + Kahan fold ----
        #pragma unroll
        for (int k8 = 0; k8 < 4; k8++) {
            float tmp[2][4] = {};
            #pragma unroll
            for (int kk = 0; kk < 8; kk++) {
                int k = k8 * 8 + kk;
                float4 w = *(const float4*)&Wb[cb][k][tx * 4];
                float a0 = Ab[cb][ty * 2 + 0][k];
                float a1 = Ab[cb][ty * 2 + 1][k];
                tmp[0][0] = fmaf(a0, w.x, tmp[0][0]);
                tmp[0][1] = fmaf(a0, w.y, tmp[0][1]);
                tmp[0][2] = fmaf(a0, w.z, tmp[0][2]);
                tmp[0][3] = fmaf(a0, w.w, tmp[0][3]);
                tmp[1][0] = fmaf(a1, w.x, tmp[1][0]);
                tmp[1][1] = fmaf(a1, w.y, tmp[1][1]);
                tmp[1][2] = fmaf(a1, w.z, tmp[1][2]);
                tmp[1][3] = fmaf(a1, w.w, tmp[1][3]);
            }
            #pragma unroll
            for (int r = 0; r < 2; r++)
                #pragma unroll
                for (int cq = 0; cq < 4; cq++)
                    KAHAN_ADD(acc[r][cq], cmp[r][cq], tmp[r][cq]);
        }
        __syncthreads();          // all reads of buf cb done before it is refilled
    }

    // ---- final scalar input column (x_t for enc, dec_in for dec) ----
    int jb = jc + tx * 4;
    float4 wlast = *(const float4*)&W[KMAIN * G4 + jb];
    #pragma unroll
    for (int r = 0; r < 2; r++) {
        int b = rb + ty * 2 + r;
        float e = is_enc ? xptr[b * S + t] : g_ext[b * 257 + 256];
        KAHAN_ADD(acc[r][0], cmp[r][0], e * wlast.x);
        KAHAN_ADD(acc[r][1], cmp[r][1], e * wlast.y);
        KAHAN_ADD(acc[r][2], cmp[r][2], e * wlast.z);
        KAHAN_ADD(acc[r][3], cmp[r][3], e * wlast.w);
    }

    int unit = (jc >> 2) + tx;
    float bi = bias[jb + 0], bf = bias[jb + 1], bg = bias[jb + 2], bo = bias[jb + 3];
    #pragma unroll
    for (int r = 0; r < 2; r++) {
        int b = rb + ty * 2 + r;
        float iv = sig_xla(acc[r][0] + bi);
        float fv = sig_xla(acc[r][1] + bf);
        float gv = tanh_xla(acc[r][2] + bg);
        float ov = sig_xla(acc[r][3] + bo);
        float cold = g_c[b * H + unit];
        float cn = fv * cold + iv * gv;
        float hh = ov * tanh_xla(cn);
        g_c[b * H + unit] = cn;
        h_out[b * H + unit] = hh;
        if (is_enc) g_enc_out[b * (S * H) + t * H + unit] = hh;
    }
}

// ---------------- encW1 precompute: [b][u][s] = enc_out[b,s,:] . W1[u,:] ----
__global__ __launch_bounds__(256) void encW1_kernel(const float* __restrict__ W1)
{
    int w = blockIdx.x * 8 + (threadIdx.x >> 5);
    int lane = threadIdx.x & 31;
    int b = w >> 8, s = w & 255;
    const float* e = g_enc_out + b * (S * H) + s * H;
    float ev[8];
    #pragma unroll
    for (int i = 0; i < 8; i++) ev[i] = e[lane + 32 * i];
    #pragma unroll
    for (int u = 0; u < U; u++) {
        float p = 0.f, c = 0.f;
        #pragma unroll
        for (int i = 0; i < 8; i++) KAHAN_ADD(p, c, ev[i] * W1[u * 256 + lane + 32 * i]);
        #pragma unroll
        for (int o = 16; o; o >>= 1) p += __shfl_xor_sync(0xffffffffu, p, o);
        if (lane == 0) g_encW1[b * (U * S) + u * S + s] = p;
    }
}

// ---------------- fused attention step (R9 exact) ---------------------------
__global__ __launch_bounds__(256) void attn_step(const float* __restrict__ x,
                                                 const void* __restrict__ yv,
                                                 const float* __restrict__ W2,
                                                 const float* __restrict__ V,
                                                 float* __restrict__ outp,
                                                 int t, int parity)
{
    const float* h_in = parity ? g_hB : g_hA;
    int b = blockIdx.x, tid = threadIdx.x;

    __shared__ float sh_h[256];
    __shared__ float sh_w2h[16];
    __shared__ float sV[16];
    __shared__ float sh_log[256];
    __shared__ float sh_aj[256];
    __shared__ float sh_red[256];
    __shared__ int   sh_idx[256];
    __shared__ float sgp[8][256];

    sh_h[tid] = h_in[b * H + tid];
    if (tid == 0) g_ext[b * 257 + 256] = g_decnext[b];
    if (tid < U)  sV[tid] = V[tid];
    __syncthreads();

    int wid = tid >> 5, lane = tid & 31;
    for (int u = wid; u < U; u += 8) {
        float p = 0.f, c = 0.f;
        #pragma unroll
        for (int k = lane; k < 256; k += 32) KAHAN_ADD(p, c, sh_h[k] * W2[u * 256 + k]);
        #pragma unroll
        for (int o = 16; o; o >>= 1) p += __shfl_xor_sync(0xffffffffu, p, o);
        if (lane == 0) sh_w2h[u] = p;
    }
    __syncthreads();

    const float* ew = g_encW1 + b * (U * S) + tid;
    float lg = 0.f, lgc = 0.f;
    #pragma unroll
    for (int u = 0; u < U; u++)
        KAHAN_ADD(lg, lgc, sV[u] * tanh_xla(ew[u * S] + sh_w2h[u]));
    sh_log[tid] = lg;
    sh_red[tid] = lg;
    sh_idx[tid] = tid;
    __syncthreads();

    // argmax (first occurrence on ties, matching jnp.argmax)
    #pragma unroll
    for (int off = 128; off; off >>= 1) {
        if (tid < off) {
            float ov = sh_red[tid + off]; int oi = sh_idx[tid + off];
            float cv = sh_red[tid];       int ci = sh_idx[tid];
            if (ov > cv || (ov == cv && oi < ci)) { sh_red[tid] = ov; sh_idx[tid] = oi; }
        }
        __syncthreads();
    }
    float mx = sh_red[0]; int mi = sh_idx[0];
    __syncthreads();

    float p = exp_p(lg - mx);
    sh_red[tid] = p;
    __syncthreads();
    #pragma unroll
    for (int off = 128; off; off >>= 1) {
        if (tid < off) sh_red[tid] += sh_red[tid + off];
        __syncthreads();
    }
    float sum = sh_red[0];
    sh_aj[tid] = __fdiv_rn(p, sum);

    if (tid == 0) {
        int yi = g_y64 ? (int)((const long long*)yv)[b * S + t]
                       : ((const int*)yv)[b * S + t];
        float logpy = sh_log[yi] - mx - (float)log((double)sum);
        g_lossbuf[t * B + b] = -logpy;
        outp[t * B + b] = (float)mi;
        g_decnext[b] = x[b * S + yi];
    }
    __syncthreads();

    // di[b][h] = sum_s aj[s] * enc_out[b][s][h]
    {
        int hc = tid & 31;
        int sg = tid >> 5;
        const float* eb = g_enc_out + (size_t)b * (S * H) + hc * 8;
        float a[8] = {}, cc[8] = {};
        int sbase = sg * 32;
        bool persist = (b < B_PERSIST);
        #pragma unroll
        for (int c8 = 0; c8 < 4; c8++) {
            float tmp[8] = {};
            #pragma unroll
            for (int kk = 0; kk < 8; kk++) {
                int s2 = sbase + c8 * 8 + kk;
                float e[8];
                if (persist) ld8_last(eb + (size_t)s2 * H, e);
                else         ld8_first(eb + (size_t)s2 * H, e);
                float aw = sh_aj[s2];
                #pragma unroll
                for (int j = 0; j < 8; j++) tmp[j] = fmaf(aw, e[j], tmp[j]);
            }
            #pragma unroll
            for (int j = 0; j < 8; j++) KAHAN_ADD(a[j], cc[j], tmp[j]);
        }
        #pragma unroll
        for (int j = 0; j < 8; j++) sgp[sg][hc * 8 + j] = a[j];
    }
    __syncthreads();
    {
        float a = sgp[0][tid], c = 0.f;
        #pragma unroll
        for (int g = 1; g < 8; g++) KAHAN_ADD(a, c, sgp[g][tid]);
        g_ext[b * 257 + tid] = a;
    }
}

// ---------------- deterministic loss reduction ------------------------------
__global__ void loss_reduce(float* __restrict__ outp, int do_write)
{
    __shared__ float sr[256];
    int tid = threadIdx.x;
    float a = 0.f, c = 0.f;
    for (int i = tid; i < S * B; i += 256) KAHAN_ADD(a, c, g_lossbuf[i]);
    sr[tid] = a;
    __syncthreads();
    #pragma unroll
    for (int off = 128; off; off >>= 1) {
        if (tid < off) sr[tid] += sr[tid + off];
        __syncthreads();
    }
    if (tid == 0 && do_write) outp[S * B] = __fdiv_rn(sr[0], 512.f * 512.f);
}

// ---------------- host launch ----------------------------------------------
extern "C" void kernel_launch(void* const* d_in, const int* in_sizes, int n_in,
                              void* d_out, int out_size)
{
    const float* x    = (const float*)d_in[0];
    const void*  y    = d_in[1];
    const float* eWih = (const float*)d_in[2];
    const float* eWhh = (const float*)d_in[3];
    const float* ebih = (const float*)d_in[4];
    const float* ebhh = (const float*)d_in[5];
    const float* dWih = (const float*)d_in[6];
    const float* dWhh = (const float*)d_in[7];
    const float* dbih = (const float*)d_in[8];
    const float* dbhh = (const float*)d_in[9];
    const float* W1   = (const float*)d_in[10];
    const float* W2   = (const float*)d_in[11];
    const float* V    = (const float*)d_in[12];
    float* outp = (float*)d_out;

    prep_kernel<<<(513 * G4 + 255) / 256, 256>>>(eWih, eWhh, ebih, ebhh,
                                                 dWih, dWhh, dbih, dbhh);
    init_kernel<<<(B * H + 255) / 256, 256>>>();
    detect_y<<<1, 1>>>(y);

    dim3 grid(G4 / 64, B / 32);   // 16 x 16 = 256 CTAs

    // encoder (KMAIN=256, x_t handled in epilogue)
    for (int t = 0; t < S; t++)
        lstm_step<<<grid, 256>>>(x, 256, 1, t, t & 1);

    encW1_kernel<<<B * S / 8, 256>>>(W1);

    // decoder (KMAIN=512, dec_in handled in epilogue).
    // t = S-1 lstm output is unused by the reference -> skip it.
    for (int t = 0; t < S; t++) {
        attn_step<<<B, 256>>>(x, y, W2, V, outp, t, t & 1);
        if (t < S - 1) lstm_step<<<grid, 256>>>(x, 512, 0, t, t & 1);
    }

    loss_reduce<<<1, 256>>>(outp, out_size > S * B ? 1 : 0);
}